// round 13
// baseline (speedup 1.0000x reference)
#include <cuda_runtime.h>
#include <cuda_fp16.h>
#include <cstdint>

#define D   256
#define KC  1024
#define M_ROWS 65536

// ---- filter smem: enorm table + fp16 A tile ----
#define FS_EN   0                  // 1024 floats = 4096 B
#define FS_A    4096               // 128 rows x 264 fp16 = 67584 B
#define FS_TOTAL 71680
#define AW_STRIDE 132              // uint32 words per A row (264 fp16 / 2)

#define WINF 2.5e-4f

// rowscan smem: 128 codes x 260 floats + x row (260) + pad
#define RS_SMEM ((128 * 260 + 260 + 12) * 4)

__device__ double g_loss_accum;
__device__ int    g_cnt2, g_cnt3;
__device__ __align__(16) float g_enorm[KC];
__device__ __align__(16) float g_xn[M_ROWS];
__device__ __align__(16) int   g_list2[M_ROWS];
__device__ __align__(16) int2  g_pair[M_ROWS];
__device__ __align__(16) int   g_list3[M_ROWS];
// fp16 B fragments (e * 1024): [g=k32(8)][code(1024)][q(4)] x uint4
__device__ __align__(16) uint4 g_Bh[8 * 1024 * 4];

__device__ __forceinline__ void mma_fp16(float* c, const uint32_t* a, uint32_t b0, uint32_t b1) {
    asm volatile("mma.sync.aligned.m16n8k16.row.col.f32.f16.f16.f32 "
                 "{%0,%1,%2,%3}, {%4,%5,%6,%7}, {%8,%9}, {%0,%1,%2,%3};"
                 : "+f"(c[0]), "+f"(c[1]), "+f"(c[2]), "+f"(c[3])
                 : "r"(a[0]), "r"(a[1]), "r"(a[2]), "r"(a[3]), "r"(b0), "r"(b1));
}
__device__ __forceinline__ bool bt(float va, int ia, float vb, int ib) {
    return va < vb || (va == vb && ia < ib);
}

// ---------------------------------------------------------------------------
// Prep: e-norms (R2-verbatim reduction), fp16 B fragment images, zero accums.
// ---------------------------------------------------------------------------
__global__ void vq_prep(const float* __restrict__ E) {
    int code = blockIdx.x;
    int t = threadIdx.x;          // 64 threads, 4 elems each
    const float4* row = (const float4*)(E + (size_t)code * D);
    float4 v = row[t];
    float s = v.x * v.x + v.y * v.y + v.z * v.z + v.w * v.w;
    #pragma unroll
    for (int o = 16; o > 0; o >>= 1) s += __shfl_xor_sync(0xFFFFFFFFu, s, o);
    __shared__ float ws[2];
    if ((t & 31) == 0) ws[t >> 5] = s;
    __syncthreads();
    if (t == 0) {
        g_enorm[code] = ws[0] + ws[1];
        if (code == 0) { g_loss_accum = 0.0; g_cnt2 = 0; g_cnt3 = 0; }
    }

    uint32_t* W = (uint32_t*)g_Bh;
    float f[4] = {v.x, v.y, v.z, v.w};
    #pragma unroll
    for (int pp = 0; pp < 2; pp++) {
        int p = 2 * t + pp;              // pair index (k = 2p, 2p+1)
        int k16 = p >> 3, r = p & 7, h = r >> 2, q = r & 3;
        int g = k16 >> 1, comp = (k16 & 1) * 2 + h;
        __half2 hv = __floats2half2_rn(f[pp * 2] * 1024.f, f[pp * 2 + 1] * 1024.f);
        W[(((size_t)g * 1024 + code) * 4 + q) * 4 + comp] = *(uint32_t*)&hv;
    }
}

// ---------------------------------------------------------------------------
// xnorm: R2's per-row ||x||^2, verbatim structure.
// ---------------------------------------------------------------------------
__global__ void vq_xnorm(const float* __restrict__ X) {
    int tid = threadIdx.x;
    int row0 = blockIdx.x * 128;
    int r = tid >> 1, h = tid & 1;
    const float4* xr = (const float4*)(X + (size_t)(row0 + r) * D + h * 128);
    float s = 0.f;
    #pragma unroll
    for (int j = 0; j < 32; j++) {
        float4 v = xr[j];
        s += v.x * v.x + v.y * v.y + v.z * v.z + v.w * v.w;
    }
    s += __shfl_xor_sync(0xFFFFFFFFu, s, 1);
    if (h == 0) g_xn[row0 + r] = s;
}

// ---------------------------------------------------------------------------
// Filter: fp16 m16n8k16 warp-MMA, top-3 + 3-tier margin emission; confident
// rows get approx loss + fused STE; others go to pair / rowscan lists.
// ---------------------------------------------------------------------------
__global__ void __launch_bounds__(256, 2)
vq_filter(const float* __restrict__ X, const float* __restrict__ E,
          float* __restrict__ out) {
    extern __shared__ char sm[];
    __shared__ int s_code[128];
    const int tid  = threadIdx.x;
    const int lane = tid & 31;
    const int warp = tid >> 5;
    const int row0 = blockIdx.x * 128;

    float*    s_en = (float*)(sm + FS_EN);
    uint32_t* Aw   = (uint32_t*)(sm + FS_A);

    for (int i = tid; i < 128 * 64; i += 256) {
        int r = i >> 6, c4 = i & 63;
        float4 v = *(const float4*)(X + (size_t)(row0 + r) * D + c4 * 4);
        __half2 h0 = __floats2half2_rn(v.x, v.y);
        __half2 h1 = __floats2half2_rn(v.z, v.w);
        uint32_t* dst = Aw + r * AW_STRIDE + c4 * 2;
        dst[0] = *(uint32_t*)&h0;
        dst[1] = *(uint32_t*)&h1;
    }
    for (int i = tid; i < KC; i += 256) s_en[i] = g_enorm[i];
    __syncthreads();

    const int rA = warp * 16 + (lane >> 2);
    const int q  = lane & 3;
    const uint32_t* pA0 = Aw + rA * AW_STRIDE + q;
    const uint32_t* pA1 = pA0 + 8 * AW_STRIDE;

    float v1[2] = {3e38f, 3e38f}, v2[2] = {3e38f, 3e38f}, v3[2] = {3e38f, 3e38f};
    int   i1[2] = {0, 0},         i2[2] = {0, 0},         i3[2] = {0, 0};

    #define INS3(slot, sv, sidx) do { \
        float _s = (sv); int _i = (sidx); \
        if (_s < v3[slot]) { \
            if (_s < v2[slot]) { \
                v3[slot] = v2[slot]; i3[slot] = i2[slot]; \
                if (_s < v1[slot]) { v2[slot] = v1[slot]; i2[slot] = i1[slot]; \
                                     v1[slot] = _s; i1[slot] = _i; } \
                else               { v2[slot] = _s; i2[slot] = _i; } \
            } else { v3[slot] = _s; i3[slot] = _i; } \
        } } while (0)

    for (int nc = 0; nc < 8; nc++) {
        float C[16][4];
        #pragma unroll
        for (int nt = 0; nt < 16; nt++)
            #pragma unroll
            for (int j = 0; j < 4; j++) C[nt][j] = 0.f;

        #pragma unroll
        for (int g = 0; g < 8; g++) {
            uint32_t aE[4], aO[4];
            int wE = 16 * g, wO = wE + 8;
            aE[0] = pA0[wE];     aE[1] = pA1[wE];
            aE[2] = pA0[wE + 4]; aE[3] = pA1[wE + 4];
            aO[0] = pA0[wO];     aO[1] = pA1[wO];
            aO[2] = pA0[wO + 4]; aO[3] = pA1[wO + 4];
            const uint4* pb = g_Bh + ((size_t)g * 1024 + nc * 128 + (lane >> 2)) * 4 + q;
            #pragma unroll
            for (int nt = 0; nt < 16; nt++) {
                uint4 b = __ldg(pb + nt * 32);
                mma_fp16(C[nt], aE, b.x, b.y);
                mma_fp16(C[nt], aO, b.z, b.w);
            }
        }

        #pragma unroll
        for (int nt = 0; nt < 16; nt++) {
            int cl = nt * 8 + q * 2;
            int col0 = nc * 128 + cl;
            float en0 = s_en[col0], en1 = s_en[col0 + 1];
            INS3(0, __fmaf_rn(-0x1p-9f, C[nt][0], en0), col0);
            INS3(0, __fmaf_rn(-0x1p-9f, C[nt][1], en1), col0 + 1);
            INS3(1, __fmaf_rn(-0x1p-9f, C[nt][2], en0), col0);
            INS3(1, __fmaf_rn(-0x1p-9f, C[nt][3], en1), col0 + 1);
        }
    }

    // quad merge of sorted triples (lanes sharing rows)
    #pragma unroll
    for (int o = 1; o < 4; o <<= 1) {
        #pragma unroll
        for (int sl = 0; sl < 2; sl++) {
            float tv[3]; int ti[3];
            tv[0] = __shfl_xor_sync(0xFFFFFFFFu, v1[sl], o);
            ti[0] = __shfl_xor_sync(0xFFFFFFFFu, i1[sl], o);
            tv[1] = __shfl_xor_sync(0xFFFFFFFFu, v2[sl], o);
            ti[1] = __shfl_xor_sync(0xFFFFFFFFu, i2[sl], o);
            tv[2] = __shfl_xor_sync(0xFFFFFFFFu, v3[sl], o);
            ti[2] = __shfl_xor_sync(0xFFFFFFFFu, i3[sl], o);
            float mv[3] = {v1[sl], v2[sl], v3[sl]};
            int   mi[3] = {i1[sl], i2[sl], i3[sl]};
            float rv[3]; int ri[3];
            int a = 0, b = 0;
            #pragma unroll
            for (int k = 0; k < 3; k++) {
                bool ta = (b >= 3) || (a < 3 && bt(mv[a], mi[a], tv[b], ti[b]));
                rv[k] = ta ? mv[a] : tv[b];
                ri[k] = ta ? mi[a] : ti[b];
                if (ta) a++; else b++;
            }
            v1[sl] = rv[0]; i1[sl] = ri[0];
            v2[sl] = rv[1]; i2[sl] = ri[1];
            v3[sl] = rv[2]; i3[sl] = ri[2];
        }
    }

    // 3-tier emission
    float lsum = 0.f;
    if (q == 0) {
        #pragma unroll
        for (int sl = 0; sl < 2; sl++) {
            int rl  = rA + sl * 8;
            int row = row0 + rl;
            float lim = v1[sl] + WINF;
            if (v2[sl] >= lim) {
                s_code[rl] = i1[sl];
                lsum += __fadd_rn(g_xn[row], v1[sl]);   // approx loss, error ~1e-5
            } else if (v3[sl] >= lim) {
                int slot = atomicAdd(&g_cnt2, 1);
                g_list2[slot] = row;
                g_pair[slot]  = make_int2(i1[sl], i2[sl]);
                s_code[rl] = -1;
            } else {
                int slot = atomicAdd(&g_cnt3, 1);
                g_list3[slot] = row;
                s_code[rl] = -1;
            }
        }
    }
    #pragma unroll
    for (int o = 16; o > 0; o >>= 1) lsum += __shfl_xor_sync(0xFFFFFFFFu, lsum, o);
    if (lane == 0) atomicAdd(&g_loss_accum, (double)lsum);
    __syncthreads();

    // fused STE: out = fl(x + fl(q - x)); confident rows only
    for (int i = tid; i < 128 * 64; i += 256) {
        int rr = i >> 6, c4 = i & 63;
        int cd = s_code[rr];
        if (cd < 0) continue;
        float4 qv = __ldg((const float4*)(E + (size_t)cd * D + c4 * 4));
        float4 x  = *(const float4*)(X + (size_t)(row0 + rr) * D + c4 * 4);
        float4 rv;
        rv.x = __fadd_rn(x.x, __fsub_rn(qv.x, x.x));
        rv.y = __fadd_rn(x.y, __fsub_rn(qv.y, x.y));
        rv.z = __fadd_rn(x.z, __fsub_rn(qv.z, x.z));
        rv.w = __fadd_rn(x.w, __fsub_rn(qv.w, x.w));
        *(float4*)(out + (size_t)(row0 + rr) * D + c4 * 4) = rv;
    }
}

// ---------------------------------------------------------------------------
// Pair refine: exact chains for {i1, i2}; 128 rows x 2 threads per block.
// ---------------------------------------------------------------------------
__global__ void __launch_bounds__(256)
vq_pair(const float* __restrict__ X, const float* __restrict__ E,
        float* __restrict__ out) {
    __shared__ int s_row[128];
    __shared__ int s_cd[128];
    const int tid = threadIdx.x;
    const int n2 = g_cnt2;

    for (int base = blockIdx.x * 128; base < n2; base += gridDim.x * 128) {
        __syncthreads();
        if (tid < 128) {
            int idx = base + tid;
            s_row[tid] = (idx < n2) ? g_list2[idx] : -1;
        }
        __syncthreads();

        int j  = tid >> 1, cs = tid & 1;
        int row = s_row[j];
        float bv = 3e38f; int bn = 0x7FFFFFFF;
        if (row >= 0) {
            int2 pr = g_pair[base + j];
            int c = cs ? pr.y : pr.x;
            const float4* xr = (const float4*)(X + (size_t)row * D);
            const float4* er = (const float4*)(E + (size_t)c * D);
            float d = 0.f;
            #pragma unroll 8
            for (int k4 = 0; k4 < 64; k4++) {
                float4 xv = __ldg(&xr[k4]);
                float4 ev = __ldg(&er[k4]);
                d = __fmaf_rn(xv.x, ev.x, d);
                d = __fmaf_rn(xv.y, ev.y, d);
                d = __fmaf_rn(xv.z, ev.z, d);
                d = __fmaf_rn(xv.w, ev.w, d);
            }
            bv = __fmaf_rn(-2.f, d, __fadd_rn(g_xn[row], __ldg(&g_enorm[c])));
            bn = c;
        }
        float ov = __shfl_xor_sync(0xFFFFFFFFu, bv, 1);
        int   on = __shfl_xor_sync(0xFFFFFFFFu, bn, 1);
        if (bt(ov, on, bv, bn)) { bv = ov; bn = on; }
        if (row >= 0 && cs == 0) {
            s_cd[j] = bn;
            atomicAdd(&g_loss_accum, (double)bv);
        }
        __syncthreads();

        for (int idx = tid; idx < 128 * 64; idx += 256) {
            int j2 = idx >> 6, c4 = idx & 63;
            int r2 = s_row[j2];
            if (r2 < 0) continue;
            int cd = s_cd[j2];
            float4 qv = __ldg((const float4*)(E + (size_t)cd * D + c4 * 4));
            float4 x  = __ldg((const float4*)(X + (size_t)r2 * D + c4 * 4));
            float4 rv;
            rv.x = __fadd_rn(x.x, __fsub_rn(qv.x, x.x));
            rv.y = __fadd_rn(x.y, __fsub_rn(qv.y, x.y));
            rv.z = __fadd_rn(x.z, __fsub_rn(qv.z, x.z));
            rv.w = __fadd_rn(x.w, __fsub_rn(qv.w, x.w));
            *(float4*)(out + (size_t)r2 * D + c4 * 4) = rv;
        }
    }
}

// ---------------------------------------------------------------------------
// Rowscan: block-per-row, all 1024 codes as exact chains from smem-staged E.
// 128 threads; 8 tiles of 128 codes (stride 260 -> conflict-free LDS).
// ---------------------------------------------------------------------------
__global__ void __launch_bounds__(128)
vq_rowscan(const float* __restrict__ X, const float* __restrict__ E,
           float* __restrict__ out) {
    extern __shared__ float smf[];
    float* sE = smf;                 // 128 x 260
    float* sx = smf + 128 * 260;     // 260
    __shared__ float s_wv[4];
    __shared__ int   s_wn[4];
    __shared__ int   s_fin;
    const int tid  = threadIdx.x;
    const int lane = tid & 31;
    const int warp = tid >> 5;
    const int n3 = g_cnt3;

    for (int i = blockIdx.x; i < n3; i += gridDim.x) {
        const int row = g_list3[i];
        __syncthreads();
        if (tid < 64)
            *(float4*)(sx + tid * 4) = __ldg((const float4*)(X + (size_t)row * D + tid * 4));
        const float xn = g_xn[row];

        float bv = 3e38f; int bn = 0x7FFFFFFF;
        for (int t = 0; t < 8; t++) {
            __syncthreads();
            for (int idx = tid; idx < 128 * 64; idx += 128) {
                int code = idx >> 6, c4 = idx & 63;
                *(float4*)(sE + code * 260 + c4 * 4) =
                    __ldg((const float4*)(E + (size_t)(t * 128 + code) * D + c4 * 4));
            }
            __syncthreads();
            const float* er = sE + tid * 260;
            float d = 0.f;
            #pragma unroll 8
            for (int k4 = 0; k4 < 64; k4++) {
                float4 xv = *(const float4*)(sx + k4 * 4);
                float4 ev = *(const float4*)(er + k4 * 4);
                d = __fmaf_rn(xv.x, ev.x, d);
                d = __fmaf_rn(xv.y, ev.y, d);
                d = __fmaf_rn(xv.z, ev.z, d);
                d = __fmaf_rn(xv.w, ev.w, d);
            }
            int c = t * 128 + tid;
            float s = __fmaf_rn(-2.f, d, __fadd_rn(xn, __ldg(&g_enorm[c])));
            if (bt(s, c, bv, bn)) { bv = s; bn = c; }
        }
        // reduce 128 -> 1 (lowest-index ties; bt is an order-independent min)
        #pragma unroll
        for (int o = 16; o > 0; o >>= 1) {
            float ov = __shfl_xor_sync(0xFFFFFFFFu, bv, o);
            int   on = __shfl_xor_sync(0xFFFFFFFFu, bn, o);
            if (bt(ov, on, bv, bn)) { bv = ov; bn = on; }
        }
        if (lane == 0) { s_wv[warp] = bv; s_wn[warp] = bn; }
        __syncthreads();
        if (tid == 0) {
            float fv = s_wv[0]; int fn = s_wn[0];
            #pragma unroll
            for (int w = 1; w < 4; w++)
                if (bt(s_wv[w], s_wn[w], fv, fn)) { fv = s_wv[w]; fn = s_wn[w]; }
            s_fin = fn;
            atomicAdd(&g_loss_accum, (double)fv);
        }
        __syncthreads();

        int code = s_fin;
        if (tid < 64) {
            float4 qv = __ldg((const float4*)(E + (size_t)code * D + tid * 4));
            float4 x  = *(const float4*)(sx + tid * 4);
            float4 rv;
            rv.x = __fadd_rn(x.x, __fsub_rn(qv.x, x.x));
            rv.y = __fadd_rn(x.y, __fsub_rn(qv.y, x.y));
            rv.z = __fadd_rn(x.z, __fsub_rn(qv.z, x.z));
            rv.w = __fadd_rn(x.w, __fsub_rn(qv.w, x.w));
            *(float4*)(out + (size_t)row * D + tid * 4) = rv;
        }
    }
}

__global__ void vq_finish(float* __restrict__ out, int total_elems) {
    out[total_elems] = (float)(1.25 * g_loss_accum / (double)total_elems);
}

extern "C" void kernel_launch(void* const* d_in, const int* in_sizes, int n_in,
                              void* d_out, int out_size) {
    const float* X = (const float*)d_in[0];   // latents  [8192, 2048] fp32
    const float* E = (const float*)d_in[1];   // embedding [1024, 256] fp32
    float* out = (float*)d_out;
    int M = in_sizes[0] / D;                  // 65536 rows

    cudaFuncSetAttribute(vq_filter, cudaFuncAttributeMaxDynamicSharedMemorySize, FS_TOTAL);
    cudaFuncSetAttribute(vq_rowscan, cudaFuncAttributeMaxDynamicSharedMemorySize, RS_SMEM);
    vq_prep<<<KC, 64>>>(E);
    vq_xnorm<<<M / 128, 256>>>(X);
    vq_filter<<<M / 128, 256, FS_TOTAL>>>(X, E, out);
    vq_pair<<<64, 256>>>(X, E, out);
    vq_rowscan<<<128, 128, RS_SMEM>>>(X, E, out);
    vq_finish<<<1, 1>>>(out, out_size - 1);
}

// round 14
// speedup vs baseline: 1.0035x; 1.0035x over previous
#include <cuda_runtime.h>
#include <cuda_fp16.h>
#include <cstdint>

#define D   256
#define KC  1024
#define M_ROWS 65536

// ---- filter smem: enorm table + fp16 A tile ----
#define FS_EN   0                  // 1024 floats = 4096 B
#define FS_A    4096               // 128 rows x 264 fp16 = 67584 B
#define FS_TOTAL 71680
#define AW_STRIDE 132              // uint32 words per A row (264 fp16 / 2)

#define WINF 2.5e-4f

__device__ double g_loss_accum;
__device__ int    g_listcnt;
__device__ __align__(16) float g_enorm[KC];
__device__ __align__(16) float g_xn[M_ROWS];
__device__ __align__(16) int   g_list[M_ROWS];
// transposed codebook: Et[k][code] -> coalesced per-code chain loads
__device__ __align__(16) float g_Et[D * KC];
// fp16 B fragments (e * 1024): [g=k32(8)][code(1024)][q(4)] x uint4
__device__ __align__(16) uint4 g_Bh[8 * 1024 * 4];

__device__ __forceinline__ void mma_fp16(float* c, const uint32_t* a, uint32_t b0, uint32_t b1) {
    asm volatile("mma.sync.aligned.m16n8k16.row.col.f32.f16.f16.f32 "
                 "{%0,%1,%2,%3}, {%4,%5,%6,%7}, {%8,%9}, {%0,%1,%2,%3};"
                 : "+f"(c[0]), "+f"(c[1]), "+f"(c[2]), "+f"(c[3])
                 : "r"(a[0]), "r"(a[1]), "r"(a[2]), "r"(a[3]), "r"(b0), "r"(b1));
}
__device__ __forceinline__ bool bt(float va, int ia, float vb, int ib) {
    return va < vb || (va == vb && ia < ib);
}

// ---------------------------------------------------------------------------
// Prep: e-norms (R2-verbatim reduction), fp16 B fragment images, transposed
// codebook Et, zero accums.
// ---------------------------------------------------------------------------
__global__ void vq_prep(const float* __restrict__ E) {
    int code = blockIdx.x;
    int t = threadIdx.x;          // 64 threads, 4 elems each
    const float4* row = (const float4*)(E + (size_t)code * D);
    float4 v = row[t];
    float s = v.x * v.x + v.y * v.y + v.z * v.z + v.w * v.w;
    #pragma unroll
    for (int o = 16; o > 0; o >>= 1) s += __shfl_xor_sync(0xFFFFFFFFu, s, o);
    __shared__ float ws[2];
    if ((t & 31) == 0) ws[t >> 5] = s;
    __syncthreads();
    if (t == 0) {
        g_enorm[code] = ws[0] + ws[1];
        if (code == 0) { g_loss_accum = 0.0; g_listcnt = 0; }
    }

    uint32_t* W = (uint32_t*)g_Bh;
    float f[4] = {v.x, v.y, v.z, v.w};
    // transposed codebook
    #pragma unroll
    for (int e = 0; e < 4; e++)
        g_Et[(size_t)(t * 4 + e) * KC + code] = f[e];
    // fp16 fragment image (scaled x1024)
    #pragma unroll
    for (int pp = 0; pp < 2; pp++) {
        int p = 2 * t + pp;              // pair index (k = 2p, 2p+1)
        int k16 = p >> 3, r = p & 7, h = r >> 2, q = r & 3;
        int g = k16 >> 1, comp = (k16 & 1) * 2 + h;
        __half2 hv = __floats2half2_rn(f[pp * 2] * 1024.f, f[pp * 2 + 1] * 1024.f);
        W[(((size_t)g * 1024 + code) * 4 + q) * 4 + comp] = *(uint32_t*)&hv;
    }
}

// ---------------------------------------------------------------------------
// xnorm: R2's per-row ||x||^2, verbatim structure.
// ---------------------------------------------------------------------------
__global__ void vq_xnorm(const float* __restrict__ X) {
    int tid = threadIdx.x;
    int row0 = blockIdx.x * 128;
    int r = tid >> 1, h = tid & 1;
    const float4* xr = (const float4*)(X + (size_t)(row0 + r) * D + h * 128);
    float s = 0.f;
    #pragma unroll
    for (int j = 0; j < 32; j++) {
        float4 v = xr[j];
        s += v.x * v.x + v.y * v.y + v.z * v.z + v.w * v.w;
    }
    s += __shfl_xor_sync(0xFFFFFFFFu, s, 1);
    if (h == 0) g_xn[row0 + r] = s;
}

// ---------------------------------------------------------------------------
// Filter: fp16 m16n8k16 warp-MMA (R11-identical), top-2 + margin; confident
// rows get approx loss + fused STE; ambiguous rows -> rowscan list.
// ---------------------------------------------------------------------------
__global__ void __launch_bounds__(256, 2)
vq_filter(const float* __restrict__ X, const float* __restrict__ E,
          float* __restrict__ out) {
    extern __shared__ char sm[];
    __shared__ int s_code[128];
    const int tid  = threadIdx.x;
    const int lane = tid & 31;
    const int warp = tid >> 5;
    const int row0 = blockIdx.x * 128;

    float*    s_en = (float*)(sm + FS_EN);
    uint32_t* Aw   = (uint32_t*)(sm + FS_A);

    for (int i = tid; i < 128 * 64; i += 256) {
        int r = i >> 6, c4 = i & 63;
        float4 v = *(const float4*)(X + (size_t)(row0 + r) * D + c4 * 4);
        __half2 h0 = __floats2half2_rn(v.x, v.y);
        __half2 h1 = __floats2half2_rn(v.z, v.w);
        uint32_t* dst = Aw + r * AW_STRIDE + c4 * 2;
        dst[0] = *(uint32_t*)&h0;
        dst[1] = *(uint32_t*)&h1;
    }
    for (int i = tid; i < KC; i += 256) s_en[i] = g_enorm[i];
    __syncthreads();

    const int rA = warp * 16 + (lane >> 2);
    const int q  = lane & 3;
    const uint32_t* pA0 = Aw + rA * AW_STRIDE + q;
    const uint32_t* pA1 = pA0 + 8 * AW_STRIDE;

    float v1[2] = {3e38f, 3e38f}, v2[2] = {3e38f, 3e38f};
    int   i1[2] = {0, 0},         i2[2] = {0, 0};

    #define INS2(slot, sv, sidx) do { \
        float _s = (sv); int _i = (sidx); \
        if (_s < v2[slot]) { \
            if (_s < v1[slot]) { v2[slot] = v1[slot]; i2[slot] = i1[slot]; \
                                 v1[slot] = _s; i1[slot] = _i; } \
            else               { v2[slot] = _s; i2[slot] = _i; } \
        } } while (0)

    for (int nc = 0; nc < 8; nc++) {
        float C[16][4];
        #pragma unroll
        for (int nt = 0; nt < 16; nt++)
            #pragma unroll
            for (int j = 0; j < 4; j++) C[nt][j] = 0.f;

        #pragma unroll
        for (int g = 0; g < 8; g++) {
            uint32_t aE[4], aO[4];
            int wE = 16 * g, wO = wE + 8;
            aE[0] = pA0[wE];     aE[1] = pA1[wE];
            aE[2] = pA0[wE + 4]; aE[3] = pA1[wE + 4];
            aO[0] = pA0[wO];     aO[1] = pA1[wO];
            aO[2] = pA0[wO + 4]; aO[3] = pA1[wO + 4];
            const uint4* pb = g_Bh + ((size_t)g * 1024 + nc * 128 + (lane >> 2)) * 4 + q;
            #pragma unroll
            for (int nt = 0; nt < 16; nt++) {
                uint4 b = __ldg(pb + nt * 32);
                mma_fp16(C[nt], aE, b.x, b.y);
                mma_fp16(C[nt], aO, b.z, b.w);
            }
        }

        // epilogue: approx score = en - 2*dot/1024 (xn-free ranking), top-2
        #pragma unroll
        for (int nt = 0; nt < 16; nt++) {
            int cl = nt * 8 + q * 2;
            int col0 = nc * 128 + cl;
            float en0 = s_en[col0], en1 = s_en[col0 + 1];
            INS2(0, __fmaf_rn(-0x1p-9f, C[nt][0], en0), col0);
            INS2(0, __fmaf_rn(-0x1p-9f, C[nt][1], en1), col0 + 1);
            INS2(1, __fmaf_rn(-0x1p-9f, C[nt][2], en0), col0);
            INS2(1, __fmaf_rn(-0x1p-9f, C[nt][3], en1), col0 + 1);
        }
    }

    // quad merge of top-2 (lanes sharing rows)
    #pragma unroll
    for (int o = 1; o < 4; o <<= 1) {
        #pragma unroll
        for (int sl = 0; sl < 2; sl++) {
            float tv1 = __shfl_xor_sync(0xFFFFFFFFu, v1[sl], o);
            int   ti1 = __shfl_xor_sync(0xFFFFFFFFu, i1[sl], o);
            float tv2 = __shfl_xor_sync(0xFFFFFFFFu, v2[sl], o);
            int   ti2 = __shfl_xor_sync(0xFFFFFFFFu, i2[sl], o);
            if (bt(tv1, ti1, v1[sl], i1[sl])) {
                if (bt(v1[sl], i1[sl], tv2, ti2)) { v2[sl] = v1[sl]; i2[sl] = i1[sl]; }
                else                              { v2[sl] = tv2;    i2[sl] = ti2; }
                v1[sl] = tv1; i1[sl] = ti1;
            } else {
                if (bt(tv1, ti1, v2[sl], i2[sl])) { v2[sl] = tv1; i2[sl] = ti1; }
            }
        }
    }

    // emission: confident -> code + approx loss; ambiguous -> rowscan list
    float lsum = 0.f;
    if (q == 0) {
        #pragma unroll
        for (int sl = 0; sl < 2; sl++) {
            int rl  = rA + sl * 8;
            int row = row0 + rl;
            if (v2[sl] < v1[sl] + WINF) {
                int slot = atomicAdd(&g_listcnt, 1);
                g_list[slot] = row;
                s_code[rl] = -1;
            } else {
                s_code[rl] = i1[sl];
                lsum += __fadd_rn(g_xn[row], v1[sl]);   // approx loss, error ~1e-5
            }
        }
    }
    #pragma unroll
    for (int o = 16; o > 0; o >>= 1) lsum += __shfl_xor_sync(0xFFFFFFFFu, lsum, o);
    if (lane == 0) atomicAdd(&g_loss_accum, (double)lsum);
    __syncthreads();

    // fused STE: out = fl(x + fl(q - x)); confident rows only
    for (int i = tid; i < 128 * 64; i += 256) {
        int rr = i >> 6, c4 = i & 63;
        int cd = s_code[rr];
        if (cd < 0) continue;
        float4 qv = __ldg((const float4*)(E + (size_t)cd * D + c4 * 4));
        float4 x  = *(const float4*)(X + (size_t)(row0 + rr) * D + c4 * 4);
        float4 rv;
        rv.x = __fadd_rn(x.x, __fsub_rn(qv.x, x.x));
        rv.y = __fadd_rn(x.y, __fsub_rn(qv.y, x.y));
        rv.z = __fadd_rn(x.z, __fsub_rn(qv.z, x.z));
        rv.w = __fadd_rn(x.w, __fsub_rn(qv.w, x.w));
        *(float4*)(out + (size_t)(row0 + rr) * D + c4 * 4) = rv;
    }
}

// ---------------------------------------------------------------------------
// Rowscan: block-per-ambiguous-row, all 1024 codes via transposed-Et chains
// (coalesced loads, 4-way ILP). Exact snapped scores, lowest-index ties.
// ---------------------------------------------------------------------------
__global__ void __launch_bounds__(256)
vq_rowscan(const float* __restrict__ X, const float* __restrict__ E,
           float* __restrict__ out) {
    __shared__ float sx[256];
    __shared__ float s_wv[8];
    __shared__ int   s_wn[8];
    __shared__ int   s_fin;
    const int tid  = threadIdx.x;
    const int lane = tid & 31;
    const int warp = tid >> 5;
    const int n = g_listcnt;

    for (int i = blockIdx.x; i < n; i += gridDim.x) {
        const int row = g_list[i];
        __syncthreads();                 // prior iteration done with sx/s_fin
        sx[tid] = __ldg(&X[(size_t)row * D + tid]);
        __syncthreads();
        const float xn = g_xn[row];

        // 4 exact chains per thread, ascending k, coalesced Et loads
        float d0 = 0.f, d1 = 0.f, d2 = 0.f, d3 = 0.f;
        const float* et = g_Et + tid;
        #pragma unroll 8
        for (int k = 0; k < 256; k++) {
            float xv = sx[k];
            const float* p = et + (size_t)k * KC;
            d0 = __fmaf_rn(xv, __ldg(p),       d0);
            d1 = __fmaf_rn(xv, __ldg(p + 256), d1);
            d2 = __fmaf_rn(xv, __ldg(p + 512), d2);
            d3 = __fmaf_rn(xv, __ldg(p + 768), d3);
        }
        float bv; int bn;
        float s = __fmaf_rn(-2.f, d0, __fadd_rn(xn, __ldg(&g_enorm[tid])));
        bv = s; bn = tid;
        s = __fmaf_rn(-2.f, d1, __fadd_rn(xn, __ldg(&g_enorm[tid + 256])));
        if (bt(s, tid + 256, bv, bn)) { bv = s; bn = tid + 256; }
        s = __fmaf_rn(-2.f, d2, __fadd_rn(xn, __ldg(&g_enorm[tid + 512])));
        if (bt(s, tid + 512, bv, bn)) { bv = s; bn = tid + 512; }
        s = __fmaf_rn(-2.f, d3, __fadd_rn(xn, __ldg(&g_enorm[tid + 768])));
        if (bt(s, tid + 768, bv, bn)) { bv = s; bn = tid + 768; }

        #pragma unroll
        for (int o = 16; o > 0; o >>= 1) {
            float ov = __shfl_xor_sync(0xFFFFFFFFu, bv, o);
            int   on = __shfl_xor_sync(0xFFFFFFFFu, bn, o);
            if (bt(ov, on, bv, bn)) { bv = ov; bn = on; }
        }
        if (lane == 0) { s_wv[warp] = bv; s_wn[warp] = bn; }
        __syncthreads();
        if (tid == 0) {
            float fv = s_wv[0]; int fn = s_wn[0];
            #pragma unroll
            for (int w = 1; w < 8; w++)
                if (bt(s_wv[w], s_wn[w], fv, fn)) { fv = s_wv[w]; fn = s_wn[w]; }
            s_fin = fn;
            atomicAdd(&g_loss_accum, (double)fv);
        }
        __syncthreads();

        int code = s_fin;
        float qv = __ldg(&E[(size_t)code * D + tid]);
        float x  = sx[tid];
        out[(size_t)row * D + tid] = __fadd_rn(x, __fsub_rn(qv, x));
    }
}

__global__ void vq_finish(float* __restrict__ out, int total_elems) {
    out[total_elems] = (float)(1.25 * g_loss_accum / (double)total_elems);
}

extern "C" void kernel_launch(void* const* d_in, const int* in_sizes, int n_in,
                              void* d_out, int out_size) {
    const float* X = (const float*)d_in[0];   // latents  [8192, 2048] fp32
    const float* E = (const float*)d_in[1];   // embedding [1024, 256] fp32
    float* out = (float*)d_out;
    int M = in_sizes[0] / D;                  // 65536 rows

    cudaFuncSetAttribute(vq_filter, cudaFuncAttributeMaxDynamicSharedMemorySize, FS_TOTAL);
    vq_prep<<<KC, 64>>>(E);
    vq_xnorm<<<M / 128, 256>>>(X);
    vq_filter<<<M / 128, 256, FS_TOTAL>>>(X, E, out);
    vq_rowscan<<<1024, 256>>>(X, E, out);
    vq_finish<<<1, 1>>>(out, out_size - 1);
}

// round 15
// speedup vs baseline: 1.7067x; 1.7007x over previous
#include <cuda_runtime.h>
#include <cuda_fp16.h>
#include <cstdint>

#define D   256
#define KC  1024
#define M_ROWS 65536

// ---- filter smem: enorm table + fp16 A tile ----
#define FS_EN   0                  // 1024 floats = 4096 B
#define FS_A    4096               // 128 rows x 264 fp16 = 67584 B
#define FS_TOTAL 71680
#define AW_STRIDE 132              // uint32 words per A row (264 fp16 / 2)

#define WINF 2.5e-4f
#define MAXC 16

__device__ double g_loss_accum;
__device__ int    g_listcnt, g_ofcnt;
__device__ __align__(16) float g_enorm[KC];
__device__ __align__(16) float g_xn[M_ROWS];
__device__ __align__(16) float g_v1[M_ROWS];
__device__ __align__(16) int   g_list[M_ROWS];
__device__ __align__(16) int   g_oflist[M_ROWS];
__device__ __align__(16) int   g_ccnt[M_ROWS];
__device__ __align__(16) int   g_ccodes[M_ROWS * MAXC];
// transposed codebook: Et[k][code] (overflow rowscan)
__device__ __align__(16) float g_Et[D * KC];
// fp16 B fragments (e * 1024): [g=k32(8)][code(1024)][q(4)] x uint4
__device__ __align__(16) uint4 g_Bh[8 * 1024 * 4];

__device__ __forceinline__ void mma_fp16(float* c, const uint32_t* a, uint32_t b0, uint32_t b1) {
    asm volatile("mma.sync.aligned.m16n8k16.row.col.f32.f16.f16.f32 "
                 "{%0,%1,%2,%3}, {%4,%5,%6,%7}, {%8,%9}, {%0,%1,%2,%3};"
                 : "+f"(c[0]), "+f"(c[1]), "+f"(c[2]), "+f"(c[3])
                 : "r"(a[0]), "r"(a[1]), "r"(a[2]), "r"(a[3]), "r"(b0), "r"(b1));
}
__device__ __forceinline__ bool bt(float va, int ia, float vb, int ib) {
    return va < vb || (va == vb && ia < ib);
}

// ---------------------------------------------------------------------------
// Prep: e-norms (R2-verbatim), fp16 B fragments, Et transpose, zero accums.
// ---------------------------------------------------------------------------
__global__ void vq_prep(const float* __restrict__ E) {
    int code = blockIdx.x;
    int t = threadIdx.x;          // 64 threads, 4 elems each
    const float4* row = (const float4*)(E + (size_t)code * D);
    float4 v = row[t];
    float s = v.x * v.x + v.y * v.y + v.z * v.z + v.w * v.w;
    #pragma unroll
    for (int o = 16; o > 0; o >>= 1) s += __shfl_xor_sync(0xFFFFFFFFu, s, o);
    __shared__ float ws[2];
    if ((t & 31) == 0) ws[t >> 5] = s;
    __syncthreads();
    if (t == 0) {
        g_enorm[code] = ws[0] + ws[1];
        if (code == 0) { g_loss_accum = 0.0; g_listcnt = 0; g_ofcnt = 0; }
    }

    uint32_t* W = (uint32_t*)g_Bh;
    float f[4] = {v.x, v.y, v.z, v.w};
    #pragma unroll
    for (int e = 0; e < 4; e++)
        g_Et[(size_t)(t * 4 + e) * KC + code] = f[e];
    #pragma unroll
    for (int pp = 0; pp < 2; pp++) {
        int p = 2 * t + pp;              // pair index (k = 2p, 2p+1)
        int k16 = p >> 3, r = p & 7, h = r >> 2, q = r & 3;
        int g = k16 >> 1, comp = (k16 & 1) * 2 + h;
        __half2 hv = __floats2half2_rn(f[pp * 2] * 1024.f, f[pp * 2 + 1] * 1024.f);
        W[(((size_t)g * 1024 + code) * 4 + q) * 4 + comp] = *(uint32_t*)&hv;
    }
}

// ---------------------------------------------------------------------------
// xnorm: R2's per-row ||x||^2, verbatim; also zeroes per-row capture counters.
// ---------------------------------------------------------------------------
__global__ void vq_xnorm(const float* __restrict__ X) {
    int tid = threadIdx.x;
    int row0 = blockIdx.x * 128;
    int gtid = blockIdx.x * 256 + tid;
    if (gtid < M_ROWS) g_ccnt[gtid] = 0;
    if (gtid + 131072 < M_ROWS) g_ccnt[gtid + 131072] = 0;
    int r = tid >> 1, h = tid & 1;
    const float4* xr = (const float4*)(X + (size_t)(row0 + r) * D + h * 128);
    float s = 0.f;
    #pragma unroll
    for (int j = 0; j < 32; j++) {
        float4 v = xr[j];
        s += v.x * v.x + v.y * v.y + v.z * v.z + v.w * v.w;
    }
    s += __shfl_xor_sync(0xFFFFFFFFu, s, 1);
    if (h == 0) g_xn[row0 + r] = s;
}

// ---------------------------------------------------------------------------
// Filter: fp16 m16n8k16 warp-MMA (R14-identical), top-2 + margin; confident
// rows -> approx loss + fused STE; ambiguous -> list + v1 bound.
// ---------------------------------------------------------------------------
__global__ void __launch_bounds__(256, 2)
vq_filter(const float* __restrict__ X, const float* __restrict__ E,
          float* __restrict__ out) {
    extern __shared__ char sm[];
    __shared__ int s_code[128];
    const int tid  = threadIdx.x;
    const int lane = tid & 31;
    const int warp = tid >> 5;
    const int row0 = blockIdx.x * 128;

    float*    s_en = (float*)(sm + FS_EN);
    uint32_t* Aw   = (uint32_t*)(sm + FS_A);

    for (int i = tid; i < 128 * 64; i += 256) {
        int r = i >> 6, c4 = i & 63;
        float4 v = *(const float4*)(X + (size_t)(row0 + r) * D + c4 * 4);
        __half2 h0 = __floats2half2_rn(v.x, v.y);
        __half2 h1 = __floats2half2_rn(v.z, v.w);
        uint32_t* dst = Aw + r * AW_STRIDE + c4 * 2;
        dst[0] = *(uint32_t*)&h0;
        dst[1] = *(uint32_t*)&h1;
    }
    for (int i = tid; i < KC; i += 256) s_en[i] = g_enorm[i];
    __syncthreads();

    const int rA = warp * 16 + (lane >> 2);
    const int q  = lane & 3;
    const uint32_t* pA0 = Aw + rA * AW_STRIDE + q;
    const uint32_t* pA1 = pA0 + 8 * AW_STRIDE;

    float v1[2] = {3e38f, 3e38f}, v2[2] = {3e38f, 3e38f};
    int   i1[2] = {0, 0},         i2[2] = {0, 0};

    #define INS2(slot, sv, sidx) do { \
        float _s = (sv); int _i = (sidx); \
        if (_s < v2[slot]) { \
            if (_s < v1[slot]) { v2[slot] = v1[slot]; i2[slot] = i1[slot]; \
                                 v1[slot] = _s; i1[slot] = _i; } \
            else               { v2[slot] = _s; i2[slot] = _i; } \
        } } while (0)

    for (int nc = 0; nc < 8; nc++) {
        float C[16][4];
        #pragma unroll
        for (int nt = 0; nt < 16; nt++)
            #pragma unroll
            for (int j = 0; j < 4; j++) C[nt][j] = 0.f;

        #pragma unroll
        for (int g = 0; g < 8; g++) {
            uint32_t aE[4], aO[4];
            int wE = 16 * g, wO = wE + 8;
            aE[0] = pA0[wE];     aE[1] = pA1[wE];
            aE[2] = pA0[wE + 4]; aE[3] = pA1[wE + 4];
            aO[0] = pA0[wO];     aO[1] = pA1[wO];
            aO[2] = pA0[wO + 4]; aO[3] = pA1[wO + 4];
            const uint4* pb = g_Bh + ((size_t)g * 1024 + nc * 128 + (lane >> 2)) * 4 + q;
            #pragma unroll
            for (int nt = 0; nt < 16; nt++) {
                uint4 b = __ldg(pb + nt * 32);
                mma_fp16(C[nt], aE, b.x, b.y);
                mma_fp16(C[nt], aO, b.z, b.w);
            }
        }

        #pragma unroll
        for (int nt = 0; nt < 16; nt++) {
            int cl = nt * 8 + q * 2;
            int col0 = nc * 128 + cl;
            float en0 = s_en[col0], en1 = s_en[col0 + 1];
            INS2(0, __fmaf_rn(-0x1p-9f, C[nt][0], en0), col0);
            INS2(0, __fmaf_rn(-0x1p-9f, C[nt][1], en1), col0 + 1);
            INS2(1, __fmaf_rn(-0x1p-9f, C[nt][2], en0), col0);
            INS2(1, __fmaf_rn(-0x1p-9f, C[nt][3], en1), col0 + 1);
        }
    }

    // quad merge of top-2 (lanes sharing rows)
    #pragma unroll
    for (int o = 1; o < 4; o <<= 1) {
        #pragma unroll
        for (int sl = 0; sl < 2; sl++) {
            float tv1 = __shfl_xor_sync(0xFFFFFFFFu, v1[sl], o);
            int   ti1 = __shfl_xor_sync(0xFFFFFFFFu, i1[sl], o);
            float tv2 = __shfl_xor_sync(0xFFFFFFFFu, v2[sl], o);
            int   ti2 = __shfl_xor_sync(0xFFFFFFFFu, i2[sl], o);
            if (bt(tv1, ti1, v1[sl], i1[sl])) {
                if (bt(v1[sl], i1[sl], tv2, ti2)) { v2[sl] = v1[sl]; i2[sl] = i1[sl]; }
                else                              { v2[sl] = tv2;    i2[sl] = ti2; }
                v1[sl] = tv1; i1[sl] = ti1;
            } else {
                if (bt(tv1, ti1, v2[sl], i2[sl])) { v2[sl] = tv1; i2[sl] = ti1; }
            }
        }
    }

    float lsum = 0.f;
    if (q == 0) {
        #pragma unroll
        for (int sl = 0; sl < 2; sl++) {
            int rl  = rA + sl * 8;
            int row = row0 + rl;
            if (v2[sl] < v1[sl] + WINF) {
                int slot = atomicAdd(&g_listcnt, 1);
                g_list[slot] = row;
                g_v1[row] = v1[sl];
                s_code[rl] = -1;
            } else {
                s_code[rl] = i1[sl];
                lsum += __fadd_rn(g_xn[row], v1[sl]);   // approx loss, err ~1e-5
            }
        }
    }
    #pragma unroll
    for (int o = 16; o > 0; o >>= 1) lsum += __shfl_xor_sync(0xFFFFFFFFu, lsum, o);
    if (lane == 0) atomicAdd(&g_loss_accum, (double)lsum);
    __syncthreads();

    // fused STE: out = fl(x + fl(q - x)); confident rows only
    for (int i = tid; i < 128 * 64; i += 256) {
        int rr = i >> 6, c4 = i & 63;
        int cd = s_code[rr];
        if (cd < 0) continue;
        float4 qv = __ldg((const float4*)(E + (size_t)cd * D + c4 * 4));
        float4 x  = *(const float4*)(X + (size_t)(row0 + rr) * D + c4 * 4);
        float4 rv;
        rv.x = __fadd_rn(x.x, __fsub_rn(qv.x, x.x));
        rv.y = __fadd_rn(x.y, __fsub_rn(qv.y, x.y));
        rv.z = __fadd_rn(x.z, __fsub_rn(qv.z, x.z));
        rv.w = __fadd_rn(x.w, __fsub_rn(qv.w, x.w));
        *(float4*)(out + (size_t)(row0 + rr) * D + c4 * 4) = rv;
    }
}

// ---------------------------------------------------------------------------
// Capture: 16 gathered ambiguous rows per tile; same MMA body -> identical
// approx scores; append codes with score < v1+WINF to per-row lists.
// ---------------------------------------------------------------------------
__global__ void __launch_bounds__(256)
vq_capture(const float* __restrict__ X) {
    __shared__ uint32_t Aw[16 * AW_STRIDE];
    __shared__ int   s_ridx[16];   // list index (-1 pad)
    __shared__ int   s_grow[16];   // global row (-1 pad)
    __shared__ float s_bound[16];
    const int tid  = threadIdx.x;
    const int lane = tid & 31;
    const int warp = tid >> 5;
    const int n = g_listcnt;

    for (int t = blockIdx.x; t * 16 < n; t += gridDim.x) {
        __syncthreads();
        if (tid < 16) {
            int idx = t * 16 + tid;
            int row = (idx < n) ? g_list[idx] : -1;
            s_ridx[tid]  = (idx < n) ? idx : -1;
            s_grow[tid]  = row;
            s_bound[tid] = (row >= 0) ? g_v1[row] + WINF : -3e38f;
        }
        __syncthreads();
        for (int i = tid; i < 16 * 64; i += 256) {
            int r = i >> 6, c4 = i & 63;
            int row = s_grow[r];
            uint32_t w0 = 0, w1 = 0;
            if (row >= 0) {
                float4 v = __ldg((const float4*)(X + (size_t)row * D + c4 * 4));
                __half2 h0 = __floats2half2_rn(v.x, v.y);
                __half2 h1 = __floats2half2_rn(v.z, v.w);
                w0 = *(uint32_t*)&h0; w1 = *(uint32_t*)&h1;
            }
            uint32_t* dst = Aw + r * AW_STRIDE + c4 * 2;
            dst[0] = w0; dst[1] = w1;
        }
        __syncthreads();

        const int q = lane & 3;
        const uint32_t* pA0 = Aw + (lane >> 2) * AW_STRIDE + q;
        const uint32_t* pA1 = pA0 + 8 * AW_STRIDE;

        float C[16][4];
        #pragma unroll
        for (int nt = 0; nt < 16; nt++)
            #pragma unroll
            for (int j = 0; j < 4; j++) C[nt][j] = 0.f;

        #pragma unroll
        for (int g = 0; g < 8; g++) {
            uint32_t aE[4], aO[4];
            int wE = 16 * g, wO = wE + 8;
            aE[0] = pA0[wE];     aE[1] = pA1[wE];
            aE[2] = pA0[wE + 4]; aE[3] = pA1[wE + 4];
            aO[0] = pA0[wO];     aO[1] = pA1[wO];
            aO[2] = pA0[wO + 4]; aO[3] = pA1[wO + 4];
            const uint4* pb = g_Bh + ((size_t)g * 1024 + warp * 128 + (lane >> 2)) * 4 + q;
            #pragma unroll
            for (int nt = 0; nt < 16; nt++) {
                uint4 b = __ldg(pb + nt * 32);
                mma_fp16(C[nt], aE, b.x, b.y);
                mma_fp16(C[nt], aO, b.z, b.w);
            }
        }

        int r0 = lane >> 2, r1 = r0 + 8;
        #pragma unroll
        for (int nt = 0; nt < 16; nt++) {
            int cl = nt * 8 + q * 2;
            int code0 = warp * 128 + cl;
            float en0 = __ldg(&g_enorm[code0]);
            float en1 = __ldg(&g_enorm[code0 + 1]);
            float sc;
            sc = __fmaf_rn(-0x1p-9f, C[nt][0], en0);
            if (sc < s_bound[r0]) {
                int ridx = s_ridx[r0];
                int sl = atomicAdd(&g_ccnt[ridx], 1);
                if (sl < MAXC) g_ccodes[ridx * MAXC + sl] = code0;
            }
            sc = __fmaf_rn(-0x1p-9f, C[nt][1], en1);
            if (sc < s_bound[r0]) {
                int ridx = s_ridx[r0];
                int sl = atomicAdd(&g_ccnt[ridx], 1);
                if (sl < MAXC) g_ccodes[ridx * MAXC + sl] = code0 + 1;
            }
            sc = __fmaf_rn(-0x1p-9f, C[nt][2], en0);
            if (sc < s_bound[r1]) {
                int ridx = s_ridx[r1];
                int sl = atomicAdd(&g_ccnt[ridx], 1);
                if (sl < MAXC) g_ccodes[ridx * MAXC + sl] = code0;
            }
            sc = __fmaf_rn(-0x1p-9f, C[nt][3], en1);
            if (sc < s_bound[r1]) {
                int ridx = s_ridx[r1];
                int sl = atomicAdd(&g_ccnt[ridx], 1);
                if (sl < MAXC) g_ccodes[ridx * MAXC + sl] = code0 + 1;
            }
        }
    }
}

// ---------------------------------------------------------------------------
// Refine: warp per ambiguous row, lane-per-candidate exact chains, bt-min,
// exact loss + STE. Overflow (>MAXC candidates) -> OF list.
// ---------------------------------------------------------------------------
__global__ void __launch_bounds__(256)
vq_refine(const float* __restrict__ X, const float* __restrict__ E,
          float* __restrict__ out) {
    const int tid  = threadIdx.x;
    const int lane = tid & 31;
    const int gw   = (blockIdx.x * 256 + tid) >> 5;
    const int nw   = gridDim.x * 8;
    const int n = g_listcnt;

    for (int idx = gw; idx < n; idx += nw) {
        int row = g_list[idx];
        int cnt = g_ccnt[idx];
        if (cnt > MAXC) {
            if (lane == 0) {
                int s = atomicAdd(&g_ofcnt, 1);
                g_oflist[s] = row;
            }
            continue;
        }
        float bv = 3e38f; int bn = 0x7FFFFFFF;
        if (lane < cnt) {
            int c = g_ccodes[idx * MAXC + lane];
            const float4* xr = (const float4*)(X + (size_t)row * D);
            const float4* er = (const float4*)(E + (size_t)c * D);
            float d = 0.f;
            #pragma unroll 8
            for (int k4 = 0; k4 < 64; k4++) {
                float4 xv = __ldg(&xr[k4]);
                float4 ev = __ldg(&er[k4]);
                d = __fmaf_rn(xv.x, ev.x, d);
                d = __fmaf_rn(xv.y, ev.y, d);
                d = __fmaf_rn(xv.z, ev.z, d);
                d = __fmaf_rn(xv.w, ev.w, d);
            }
            bv = __fmaf_rn(-2.f, d, __fadd_rn(g_xn[row], __ldg(&g_enorm[c])));
            bn = c;
        }
        #pragma unroll
        for (int o = 16; o > 0; o >>= 1) {
            float ov = __shfl_xor_sync(0xFFFFFFFFu, bv, o);
            int   on = __shfl_xor_sync(0xFFFFFFFFu, bn, o);
            if (bt(ov, on, bv, bn)) { bv = ov; bn = on; }
        }
        if (lane == 0) atomicAdd(&g_loss_accum, (double)bv);
        // STE: 64 float4 / 32 lanes
        #pragma unroll
        for (int u = 0; u < 2; u++) {
            int c4 = lane + u * 32;
            float4 qv = __ldg((const float4*)(E + (size_t)bn * D + c4 * 4));
            float4 x  = __ldg((const float4*)(X + (size_t)row * D + c4 * 4));
            float4 rv;
            rv.x = __fadd_rn(x.x, __fsub_rn(qv.x, x.x));
            rv.y = __fadd_rn(x.y, __fsub_rn(qv.y, x.y));
            rv.z = __fadd_rn(x.z, __fsub_rn(qv.z, x.z));
            rv.w = __fadd_rn(x.w, __fsub_rn(qv.w, x.w));
            *(float4*)(out + (size_t)row * D + c4 * 4) = rv;
        }
    }
}

// ---------------------------------------------------------------------------
// Overflow rowscan (rare): block-per-row, all 1024 codes via Et chains.
// ---------------------------------------------------------------------------
__global__ void __launch_bounds__(256)
vq_rowscan(const float* __restrict__ X, const float* __restrict__ E,
           float* __restrict__ out) {
    __shared__ float sx[256];
    __shared__ float s_wv[8];
    __shared__ int   s_wn[8];
    __shared__ int   s_fin;
    const int tid  = threadIdx.x;
    const int lane = tid & 31;
    const int warp = tid >> 5;
    const int n = g_ofcnt;

    for (int i = blockIdx.x; i < n; i += gridDim.x) {
        const int row = g_oflist[i];
        __syncthreads();
        sx[tid] = __ldg(&X[(size_t)row * D + tid]);
        __syncthreads();
        const float xn = g_xn[row];

        float d0 = 0.f, d1 = 0.f, d2 = 0.f, d3 = 0.f;
        const float* et = g_Et + tid;
        #pragma unroll 8
        for (int k = 0; k < 256; k++) {
            float xv = sx[k];
            const float* p = et + (size_t)k * KC;
            d0 = __fmaf_rn(xv, __ldg(p),       d0);
            d1 = __fmaf_rn(xv, __ldg(p + 256), d1);
            d2 = __fmaf_rn(xv, __ldg(p + 512), d2);
            d3 = __fmaf_rn(xv, __ldg(p + 768), d3);
        }
        float bv; int bn;
        float s = __fmaf_rn(-2.f, d0, __fadd_rn(xn, __ldg(&g_enorm[tid])));
        bv = s; bn = tid;
        s = __fmaf_rn(-2.f, d1, __fadd_rn(xn, __ldg(&g_enorm[tid + 256])));
        if (bt(s, tid + 256, bv, bn)) { bv = s; bn = tid + 256; }
        s = __fmaf_rn(-2.f, d2, __fadd_rn(xn, __ldg(&g_enorm[tid + 512])));
        if (bt(s, tid + 512, bv, bn)) { bv = s; bn = tid + 512; }
        s = __fmaf_rn(-2.f, d3, __fadd_rn(xn, __ldg(&g_enorm[tid + 768])));
        if (bt(s, tid + 768, bv, bn)) { bv = s; bn = tid + 768; }

        #pragma unroll
        for (int o = 16; o > 0; o >>= 1) {
            float ov = __shfl_xor_sync(0xFFFFFFFFu, bv, o);
            int   on = __shfl_xor_sync(0xFFFFFFFFu, bn, o);
            if (bt(ov, on, bv, bn)) { bv = ov; bn = on; }
        }
        if (lane == 0) { s_wv[warp] = bv; s_wn[warp] = bn; }
        __syncthreads();
        if (tid == 0) {
            float fv = s_wv[0]; int fn = s_wn[0];
            #pragma unroll
            for (int w = 1; w < 8; w++)
                if (bt(s_wv[w], s_wn[w], fv, fn)) { fv = s_wv[w]; fn = s_wn[w]; }
            s_fin = fn;
            atomicAdd(&g_loss_accum, (double)fv);
        }
        __syncthreads();

        int code = s_fin;
        float qv = __ldg(&E[(size_t)code * D + tid]);
        float x  = sx[tid];
        out[(size_t)row * D + tid] = __fadd_rn(x, __fsub_rn(qv, x));
    }
}

__global__ void vq_finish(float* __restrict__ out, int total_elems) {
    out[total_elems] = (float)(1.25 * g_loss_accum / (double)total_elems);
}

extern "C" void kernel_launch(void* const* d_in, const int* in_sizes, int n_in,
                              void* d_out, int out_size) {
    const float* X = (const float*)d_in[0];   // latents  [8192, 2048] fp32
    const float* E = (const float*)d_in[1];   // embedding [1024, 256] fp32
    float* out = (float*)d_out;
    int M = in_sizes[0] / D;                  // 65536 rows

    cudaFuncSetAttribute(vq_filter, cudaFuncAttributeMaxDynamicSharedMemorySize, FS_TOTAL);
    vq_prep<<<KC, 64>>>(E);
    vq_xnorm<<<M / 128, 256>>>(X);
    vq_filter<<<M / 128, 256, FS_TOTAL>>>(X, E, out);
    vq_capture<<<512, 256>>>(X);
    vq_refine<<<256, 256>>>(X, E, out);
    vq_rowscan<<<128, 256>>>(X, E, out);
    vq_finish<<<1, 1>>>(out, out_size - 1);
}

// round 16
// speedup vs baseline: 1.7962x; 1.0524x over previous
#include <cuda_runtime.h>
#include <cuda_fp16.h>
#include <cstdint>

#define D   256
#define KC  1024
#define M_ROWS 65536

// ---- filter smem: enorm table + fp16 A tile + B double buffer ----
#define FS_EN   0                  // 1024 floats = 4096 B
#define FS_A    4096               // 128 rows x 264 fp16 = 67584 B
#define FS_B    71680              // 2 x 8192 B stage buffers
#define FS_TOTAL 88064
#define AW_STRIDE 132              // uint32 words per A row (264 fp16 / 2)

#define WINF 2.5e-4f
#define MAXC 16

__device__ double g_loss_accum;
__device__ int    g_listcnt, g_ofcnt;
__device__ __align__(16) float g_enorm[KC];
__device__ __align__(16) float g_xn[M_ROWS];
__device__ __align__(16) float g_v1[M_ROWS];
__device__ __align__(16) int   g_list[M_ROWS];
__device__ __align__(16) int   g_oflist[M_ROWS];
__device__ __align__(16) int   g_ccnt[M_ROWS];
__device__ __align__(16) int   g_ccodes[M_ROWS * MAXC];
// transposed codebook: Et[k][code] (overflow rowscan)
__device__ __align__(16) float g_Et[D * KC];
// fp16 B fragments (e * 1024): [g=k32(8)][code(1024)][q(4)] x uint4
// NOTE: for fixed g, codes c0..c0+127 form one contiguous 8KB block.
__device__ __align__(16) uint4 g_Bh[8 * 1024 * 4];

__device__ __forceinline__ uint32_t smem_u32(const void* p) {
    uint32_t a;
    asm("{ .reg .u64 t; cvta.to.shared.u64 t, %1; cvt.u32.u64 %0, t; }" : "=r"(a) : "l"(p));
    return a;
}
__device__ __forceinline__ void mma_fp16(float* c, const uint32_t* a, uint32_t b0, uint32_t b1) {
    asm volatile("mma.sync.aligned.m16n8k16.row.col.f32.f16.f16.f32 "
                 "{%0,%1,%2,%3}, {%4,%5,%6,%7}, {%8,%9}, {%0,%1,%2,%3};"
                 : "+f"(c[0]), "+f"(c[1]), "+f"(c[2]), "+f"(c[3])
                 : "r"(a[0]), "r"(a[1]), "r"(a[2]), "r"(a[3]), "r"(b0), "r"(b1));
}
__device__ __forceinline__ bool bt(float va, int ia, float vb, int ib) {
    return va < vb || (va == vb && ia < ib);
}

// ---------------------------------------------------------------------------
// Prep: e-norms (R2-verbatim), fp16 B fragments, Et transpose, zero accums.
// ---------------------------------------------------------------------------
__global__ void vq_prep(const float* __restrict__ E) {
    int code = blockIdx.x;
    int t = threadIdx.x;          // 64 threads, 4 elems each
    const float4* row = (const float4*)(E + (size_t)code * D);
    float4 v = row[t];
    float s = v.x * v.x + v.y * v.y + v.z * v.z + v.w * v.w;
    #pragma unroll
    for (int o = 16; o > 0; o >>= 1) s += __shfl_xor_sync(0xFFFFFFFFu, s, o);
    __shared__ float ws[2];
    if ((t & 31) == 0) ws[t >> 5] = s;
    __syncthreads();
    if (t == 0) {
        g_enorm[code] = ws[0] + ws[1];
        if (code == 0) { g_loss_accum = 0.0; g_listcnt = 0; g_ofcnt = 0; }
    }

    uint32_t* W = (uint32_t*)g_Bh;
    float f[4] = {v.x, v.y, v.z, v.w};
    #pragma unroll
    for (int e = 0; e < 4; e++)
        g_Et[(size_t)(t * 4 + e) * KC + code] = f[e];
    #pragma unroll
    for (int pp = 0; pp < 2; pp++) {
        int p = 2 * t + pp;              // pair index (k = 2p, 2p+1)
        int k16 = p >> 3, r = p & 7, h = r >> 2, q = r & 3;
        int g = k16 >> 1, comp = (k16 & 1) * 2 + h;
        __half2 hv = __floats2half2_rn(f[pp * 2] * 1024.f, f[pp * 2 + 1] * 1024.f);
        W[(((size_t)g * 1024 + code) * 4 + q) * 4 + comp] = *(uint32_t*)&hv;
    }
}

// ---------------------------------------------------------------------------
// xnorm: R2's per-row ||x||^2, verbatim; also zeroes per-row capture counters.
// ---------------------------------------------------------------------------
__global__ void vq_xnorm(const float* __restrict__ X) {
    int tid = threadIdx.x;
    int row0 = blockIdx.x * 128;
    int gtid = blockIdx.x * 256 + tid;
    if (gtid < M_ROWS) g_ccnt[gtid] = 0;
    if (gtid + 131072 < M_ROWS) g_ccnt[gtid + 131072] = 0;
    int r = tid >> 1, h = tid & 1;
    const float4* xr = (const float4*)(X + (size_t)(row0 + r) * D + h * 128);
    float s = 0.f;
    #pragma unroll
    for (int j = 0; j < 32; j++) {
        float4 v = xr[j];
        s += v.x * v.x + v.y * v.y + v.z * v.z + v.w * v.w;
    }
    s += __shfl_xor_sync(0xFFFFFFFFu, s, 1);
    if (h == 0) g_xn[row0 + r] = s;
}

// ---------------------------------------------------------------------------
// Filter: fp16 m16n8k16 warp-MMA with cp.async smem-staged B (8x traffic cut,
// double-buffered). Top-2 + margin; confident rows -> approx loss + fused STE;
// ambiguous -> list + v1 bound. Scores bit-identical to capture's.
// ---------------------------------------------------------------------------
__global__ void __launch_bounds__(256, 2)
vq_filter(const float* __restrict__ X, const float* __restrict__ E,
          float* __restrict__ out) {
    extern __shared__ char sm[];
    __shared__ int s_code[128];
    const int tid  = threadIdx.x;
    const int lane = tid & 31;
    const int warp = tid >> 5;
    const int row0 = blockIdx.x * 128;

    float*    s_en = (float*)(sm + FS_EN);
    uint32_t* Aw   = (uint32_t*)(sm + FS_A);
    const uint32_t bufB = smem_u32(sm + FS_B);

    for (int i = tid; i < 128 * 64; i += 256) {
        int r = i >> 6, c4 = i & 63;
        float4 v = *(const float4*)(X + (size_t)(row0 + r) * D + c4 * 4);
        __half2 h0 = __floats2half2_rn(v.x, v.y);
        __half2 h1 = __floats2half2_rn(v.z, v.w);
        uint32_t* dst = Aw + r * AW_STRIDE + c4 * 2;
        dst[0] = *(uint32_t*)&h0;
        dst[1] = *(uint32_t*)&h1;
    }
    for (int i = tid; i < KC; i += 256) s_en[i] = g_enorm[i];

    // preload stage 0 (nc=0, g=0 -> g_Bh offset 0, contiguous 8KB)
    {
        const char* src = (const char*)g_Bh;
        asm volatile("cp.async.cg.shared.global [%0], [%1], 16;"
                     :: "r"(bufB + tid * 16), "l"(src + tid * 16));
        asm volatile("cp.async.cg.shared.global [%0], [%1], 16;"
                     :: "r"(bufB + (tid + 256) * 16), "l"(src + (tid + 256) * 16));
        asm volatile("cp.async.commit_group;" ::: "memory");
    }
    __syncthreads();

    const int rA = warp * 16 + (lane >> 2);
    const int q  = lane & 3;
    const uint32_t* pA0 = Aw + rA * AW_STRIDE + q;
    const uint32_t* pA1 = pA0 + 8 * AW_STRIDE;

    float v1[2] = {3e38f, 3e38f}, v2[2] = {3e38f, 3e38f};
    int   i1[2] = {0, 0},         i2[2] = {0, 0};

    #define INS2(slot, sv, sidx) do { \
        float _s = (sv); int _i = (sidx); \
        if (_s < v2[slot]) { \
            if (_s < v1[slot]) { v2[slot] = v1[slot]; i2[slot] = i1[slot]; \
                                 v1[slot] = _s; i1[slot] = _i; } \
            else               { v2[slot] = _s; i2[slot] = _i; } \
        } } while (0)

    for (int nc = 0; nc < 8; nc++) {
        float C[16][4];
        #pragma unroll
        for (int nt = 0; nt < 16; nt++)
            #pragma unroll
            for (int j = 0; j < 4; j++) C[nt][j] = 0.f;

        #pragma unroll
        for (int g = 0; g < 8; g++) {
            int s = nc * 8 + g;
            if (s < 63) {
                int s1 = s + 1;
                // stage s1: g=s1&7, codes (s1>>3)*128.. -> contiguous 8KB
                const char* src = (const char*)g_Bh
                    + (size_t)(((s1 & 7) * 1024 + (s1 >> 3) * 128) * 4) * 16;
                uint32_t dst = bufB + ((s1 & 1) ? 8192u : 0u);
                asm volatile("cp.async.cg.shared.global [%0], [%1], 16;"
                             :: "r"(dst + tid * 16), "l"(src + tid * 16));
                asm volatile("cp.async.cg.shared.global [%0], [%1], 16;"
                             :: "r"(dst + (tid + 256) * 16), "l"(src + (tid + 256) * 16));
                asm volatile("cp.async.commit_group;" ::: "memory");
                asm volatile("cp.async.wait_group 1;" ::: "memory");
            } else {
                asm volatile("cp.async.wait_group 0;" ::: "memory");
            }
            __syncthreads();      // stage s data visible to all warps

            uint32_t aE[4], aO[4];
            int wE = 16 * g, wO = wE + 8;
            aE[0] = pA0[wE];     aE[1] = pA1[wE];
            aE[2] = pA0[wE + 4]; aE[3] = pA1[wE + 4];
            aO[0] = pA0[wO];     aO[1] = pA1[wO];
            aO[2] = pA0[wO + 4]; aO[3] = pA1[wO + 4];
            const uint4* pb = (const uint4*)(sm + FS_B + ((s & 1) ? 8192 : 0)) + lane;
            #pragma unroll
            for (int nt = 0; nt < 16; nt++) {
                uint4 b = pb[nt * 32];
                mma_fp16(C[nt], aE, b.x, b.y);
                mma_fp16(C[nt], aO, b.z, b.w);
            }
            __syncthreads();      // all warps done reading buf before overwrite
        }

        // epilogue: approx score = en - 2*dot/1024 (xn-free ranking), top-2
        #pragma unroll
        for (int nt = 0; nt < 16; nt++) {
            int cl = nt * 8 + q * 2;
            int col0 = nc * 128 + cl;
            float en0 = s_en[col0], en1 = s_en[col0 + 1];
            INS2(0, __fmaf_rn(-0x1p-9f, C[nt][0], en0), col0);
            INS2(0, __fmaf_rn(-0x1p-9f, C[nt][1], en1), col0 + 1);
            INS2(1, __fmaf_rn(-0x1p-9f, C[nt][2], en0), col0);
            INS2(1, __fmaf_rn(-0x1p-9f, C[nt][3], en1), col0 + 1);
        }
    }

    // quad merge of top-2 (lanes sharing rows)
    #pragma unroll
    for (int o = 1; o < 4; o <<= 1) {
        #pragma unroll
        for (int sl = 0; sl < 2; sl++) {
            float tv1 = __shfl_xor_sync(0xFFFFFFFFu, v1[sl], o);
            int   ti1 = __shfl_xor_sync(0xFFFFFFFFu, i1[sl], o);
            float tv2 = __shfl_xor_sync(0xFFFFFFFFu, v2[sl], o);
            int   ti2 = __shfl_xor_sync(0xFFFFFFFFu, i2[sl], o);
            if (bt(tv1, ti1, v1[sl], i1[sl])) {
                if (bt(v1[sl], i1[sl], tv2, ti2)) { v2[sl] = v1[sl]; i2[sl] = i1[sl]; }
                else                              { v2[sl] = tv2;    i2[sl] = ti2; }
                v1[sl] = tv1; i1[sl] = ti1;
            } else {
                if (bt(tv1, ti1, v2[sl], i2[sl])) { v2[sl] = tv1; i2[sl] = ti1; }
            }
        }
    }

    float lsum = 0.f;
    if (q == 0) {
        #pragma unroll
        for (int sl = 0; sl < 2; sl++) {
            int rl  = rA + sl * 8;
            int row = row0 + rl;
            if (v2[sl] < v1[sl] + WINF) {
                int slot = atomicAdd(&g_listcnt, 1);
                g_list[slot] = row;
                g_v1[row] = v1[sl];
                s_code[rl] = -1;
            } else {
                s_code[rl] = i1[sl];
                lsum += __fadd_rn(g_xn[row], v1[sl]);   // approx loss, err ~1e-5
            }
        }
    }
    #pragma unroll
    for (int o = 16; o > 0; o >>= 1) lsum += __shfl_xor_sync(0xFFFFFFFFu, lsum, o);
    if (lane == 0) atomicAdd(&g_loss_accum, (double)lsum);
    __syncthreads();

    // fused STE: out = fl(x + fl(q - x)); confident rows only
    for (int i = tid; i < 128 * 64; i += 256) {
        int rr = i >> 6, c4 = i & 63;
        int cd = s_code[rr];
        if (cd < 0) continue;
        float4 qv = __ldg((const float4*)(E + (size_t)cd * D + c4 * 4));
        float4 x  = *(const float4*)(X + (size_t)(row0 + rr) * D + c4 * 4);
        float4 rv;
        rv.x = __fadd_rn(x.x, __fsub_rn(qv.x, x.x));
        rv.y = __fadd_rn(x.y, __fsub_rn(qv.y, x.y));
        rv.z = __fadd_rn(x.z, __fsub_rn(qv.z, x.z));
        rv.w = __fadd_rn(x.w, __fsub_rn(qv.w, x.w));
        *(float4*)(out + (size_t)(row0 + rr) * D + c4 * 4) = rv;
    }
}

// ---------------------------------------------------------------------------
// Capture: 16 gathered ambiguous rows per tile; same MMA body -> identical
// approx scores; append codes with score < v1+WINF to per-row lists.
// ---------------------------------------------------------------------------
__global__ void __launch_bounds__(256)
vq_capture(const float* __restrict__ X) {
    __shared__ uint32_t Aw[16 * AW_STRIDE];
    __shared__ int   s_ridx[16];   // list index (-1 pad)
    __shared__ int   s_grow[16];   // global row (-1 pad)
    __shared__ float s_bound[16];
    const int tid  = threadIdx.x;
    const int lane = tid & 31;
    const int warp = tid >> 5;
    const int n = g_listcnt;

    for (int t = blockIdx.x; t * 16 < n; t += gridDim.x) {
        __syncthreads();
        if (tid < 16) {
            int idx = t * 16 + tid;
            int row = (idx < n) ? g_list[idx] : -1;
            s_ridx[tid]  = (idx < n) ? idx : -1;
            s_grow[tid]  = row;
            s_bound[tid] = (row >= 0) ? g_v1[row] + WINF : -3e38f;
        }
        __syncthreads();
        for (int i = tid; i < 16 * 64; i += 256) {
            int r = i >> 6, c4 = i & 63;
            int row = s_grow[r];
            uint32_t w0 = 0, w1 = 0;
            if (row >= 0) {
                float4 v = __ldg((const float4*)(X + (size_t)row * D + c4 * 4));
                __half2 h0 = __floats2half2_rn(v.x, v.y);
                __half2 h1 = __floats2half2_rn(v.z, v.w);
                w0 = *(uint32_t*)&h0; w1 = *(uint32_t*)&h1;
            }
            uint32_t* dst = Aw + r * AW_STRIDE + c4 * 2;
            dst[0] = w0; dst[1] = w1;
        }
        __syncthreads();

        const int q = lane & 3;
        const uint32_t* pA0 = Aw + (lane >> 2) * AW_STRIDE + q;
        const uint32_t* pA1 = pA0 + 8 * AW_STRIDE;

        float C[16][4];
        #pragma unroll
        for (int nt = 0; nt < 16; nt++)
            #pragma unroll
            for (int j = 0; j < 4; j++) C[nt][j] = 0.f;

        #pragma unroll
        for (int g = 0; g < 8; g++) {
            uint32_t aE[4], aO[4];
            int wE = 16 * g, wO = wE + 8;
            aE[0] = pA0[wE];     aE[1] = pA1[wE];
            aE[2] = pA0[wE + 4]; aE[3] = pA1[wE + 4];
            aO[0] = pA0[wO];     aO[1] = pA1[wO];
            aO[2] = pA0[wO + 4]; aO[3] = pA1[wO + 4];
            const uint4* pb = g_Bh + ((size_t)g * 1024 + warp * 128 + (lane >> 2)) * 4 + q;
            #pragma unroll
            for (int nt = 0; nt < 16; nt++) {
                uint4 b = __ldg(pb + nt * 32);
                mma_fp16(C[nt], aE, b.x, b.y);
                mma_fp16(C[nt], aO, b.z, b.w);
            }
        }

        int r0 = lane >> 2, r1 = r0 + 8;
        #pragma unroll
        for (int nt = 0; nt < 16; nt++) {
            int cl = nt * 8 + q * 2;
            int code0 = warp * 128 + cl;
            float en0 = __ldg(&g_enorm[code0]);
            float en1 = __ldg(&g_enorm[code0 + 1]);
            float sc;
            sc = __fmaf_rn(-0x1p-9f, C[nt][0], en0);
            if (sc < s_bound[r0]) {
                int ridx = s_ridx[r0];
                int sl = atomicAdd(&g_ccnt[ridx], 1);
                if (sl < MAXC) g_ccodes[ridx * MAXC + sl] = code0;
            }
            sc = __fmaf_rn(-0x1p-9f, C[nt][1], en1);
            if (sc < s_bound[r0]) {
                int ridx = s_ridx[r0];
                int sl = atomicAdd(&g_ccnt[ridx], 1);
                if (sl < MAXC) g_ccodes[ridx * MAXC + sl] = code0 + 1;
            }
            sc = __fmaf_rn(-0x1p-9f, C[nt][2], en0);
            if (sc < s_bound[r1]) {
                int ridx = s_ridx[r1];
                int sl = atomicAdd(&g_ccnt[ridx], 1);
                if (sl < MAXC) g_ccodes[ridx * MAXC + sl] = code0;
            }
            sc = __fmaf_rn(-0x1p-9f, C[nt][3], en1);
            if (sc < s_bound[r1]) {
                int ridx = s_ridx[r1];
                int sl = atomicAdd(&g_ccnt[ridx], 1);
                if (sl < MAXC) g_ccodes[ridx * MAXC + sl] = code0 + 1;
            }
        }
    }
}

// ---------------------------------------------------------------------------
// Refine: warp per ambiguous row, lane-per-candidate exact chains, bt-min,
// exact loss + STE. Overflow (>MAXC candidates) -> OF list.
// ---------------------------------------------------------------------------
__global__ void __launch_bounds__(256)
vq_refine(const float* __restrict__ X, const float* __restrict__ E,
          float* __restrict__ out) {
    const int tid  = threadIdx.x;
    const int lane = tid & 31;
    const int gw   = (blockIdx.x * 256 + tid) >> 5;
    const int nw   = gridDim.x * 8;
    const int n = g_listcnt;

    for (int idx = gw; idx < n; idx += nw) {
        int row = g_list[idx];
        int cnt = g_ccnt[idx];
        if (cnt > MAXC) {
            if (lane == 0) {
                int s = atomicAdd(&g_ofcnt, 1);
                g_oflist[s] = row;
            }
            continue;
        }
        float bv = 3e38f; int bn = 0x7FFFFFFF;
        if (lane < cnt) {
            int c = g_ccodes[idx * MAXC + lane];
            const float4* xr = (const float4*)(X + (size_t)row * D);
            const float4* er = (const float4*)(E + (size_t)c * D);
            float d = 0.f;
            #pragma unroll 8
            for (int k4 = 0; k4 < 64; k4++) {
                float4 xv = __ldg(&xr[k4]);
                float4 ev = __ldg(&er[k4]);
                d = __fmaf_rn(xv.x, ev.x, d);
                d = __fmaf_rn(xv.y, ev.y, d);
                d = __fmaf_rn(xv.z, ev.z, d);
                d = __fmaf_rn(xv.w, ev.w, d);
            }
            bv = __fmaf_rn(-2.f, d, __fadd_rn(g_xn[row], __ldg(&g_enorm[c])));
            bn = c;
        }
        #pragma unroll
        for (int o = 16; o > 0; o >>= 1) {
            float ov = __shfl_xor_sync(0xFFFFFFFFu, bv, o);
            int   on = __shfl_xor_sync(0xFFFFFFFFu, bn, o);
            if (bt(ov, on, bv, bn)) { bv = ov; bn = on; }
        }
        if (lane == 0) atomicAdd(&g_loss_accum, (double)bv);
        // STE: 64 float4 / 32 lanes
        #pragma unroll
        for (int u = 0; u < 2; u++) {
            int c4 = lane + u * 32;
            float4 qv = __ldg((const float4*)(E + (size_t)bn * D + c4 * 4));
            float4 x  = __ldg((const float4*)(X + (size_t)row * D + c4 * 4));
            float4 rv;
            rv.x = __fadd_rn(x.x, __fsub_rn(qv.x, x.x));
            rv.y = __fadd_rn(x.y, __fsub_rn(qv.y, x.y));
            rv.z = __fadd_rn(x.z, __fsub_rn(qv.z, x.z));
            rv.w = __fadd_rn(x.w, __fsub_rn(qv.w, x.w));
            *(float4*)(out + (size_t)row * D + c4 * 4) = rv;
        }
    }
}

// ---------------------------------------------------------------------------
// Overflow rowscan (rare): block-per-row, all 1024 codes via Et chains.
// ---------------------------------------------------------------------------
__global__ void __launch_bounds__(256)
vq_rowscan(const float* __restrict__ X, const float* __restrict__ E,
           float* __restrict__ out) {
    __shared__ float sx[256];
    __shared__ float s_wv[8];
    __shared__ int   s_wn[8];
    __shared__ int   s_fin;
    const int tid  = threadIdx.x;
    const int lane = tid & 31;
    const int warp = tid >> 5;
    const int n = g_ofcnt;

    for (int i = blockIdx.x; i < n; i += gridDim.x) {
        const int row = g_oflist[i];
        __syncthreads();
        sx[tid] = __ldg(&X[(size_t)row * D + tid]);
        __syncthreads();
        const float xn = g_xn[row];

        float d0 = 0.f, d1 = 0.f, d2 = 0.f, d3 = 0.f;
        const float* et = g_Et + tid;
        #pragma unroll 8
        for (int k = 0; k < 256; k++) {
            float xv = sx[k];
            const float* p = et + (size_t)k * KC;
            d0 = __fmaf_rn(xv, __ldg(p),       d0);
            d1 = __fmaf_rn(xv, __ldg(p + 256), d1);
            d2 = __fmaf_rn(xv, __ldg(p + 512), d2);
            d3 = __fmaf_rn(xv, __ldg(p + 768), d3);
        }
        float bv; int bn;
        float s = __fmaf_rn(-2.f, d0, __fadd_rn(xn, __ldg(&g_enorm[tid])));
        bv = s; bn = tid;
        s = __fmaf_rn(-2.f, d1, __fadd_rn(xn, __ldg(&g_enorm[tid + 256])));
        if (bt(s, tid + 256, bv, bn)) { bv = s; bn = tid + 256; }
        s = __fmaf_rn(-2.f, d2, __fadd_rn(xn, __ldg(&g_enorm[tid + 512])));
        if (bt(s, tid + 512, bv, bn)) { bv = s; bn = tid + 512; }
        s = __fmaf_rn(-2.f, d3, __fadd_rn(xn, __ldg(&g_enorm[tid + 768])));
        if (bt(s, tid + 768, bv, bn)) { bv = s; bn = tid + 768; }

        #pragma unroll
        for (int o = 16; o > 0; o >>= 1) {
            float ov = __shfl_xor_sync(0xFFFFFFFFu, bv, o);
            int   on = __shfl_xor_sync(0xFFFFFFFFu, bn, o);
            if (bt(ov, on, bv, bn)) { bv = ov; bn = on; }
        }
        if (lane == 0) { s_wv[warp] = bv; s_wn[warp] = bn; }
        __syncthreads();
        if (tid == 0) {
            float fv = s_wv[0]; int fn = s_wn[0];
            #pragma unroll
            for (int w = 1; w < 8; w++)
                if (bt(s_wv[w], s_wn[w], fv, fn)) { fv = s_wv[w]; fn = s_wn[w]; }
            s_fin = fn;
            atomicAdd(&g_loss_accum, (double)fv);
        }
        __syncthreads();

        int code = s_fin;
        float qv = __ldg(&E[(size_t)code * D + tid]);
        float x  = sx[tid];
        out[(size_t)row * D + tid] = __fadd_rn(x, __fsub_rn(qv, x));
    }
}

__global__ void vq_finish(float* __restrict__ out, int total_elems) {
    out[total_elems] = (float)(1.25 * g_loss_accum / (double)total_elems);
}

extern "C" void kernel_launch(void* const* d_in, const int* in_sizes, int n_in,
                              void* d_out, int out_size) {
    const float* X = (const float*)d_in[0];   // latents  [8192, 2048] fp32
    const float* E = (const float*)d_in[1];   // embedding [1024, 256] fp32
    float* out = (float*)d_out;
    int M = in_sizes[0] / D;                  // 65536 rows

    cudaFuncSetAttribute(vq_filter, cudaFuncAttributeMaxDynamicSharedMemorySize, FS_TOTAL);
    vq_prep<<<KC, 64>>>(E);
    vq_xnorm<<<M / 128, 256>>>(X);
    vq_filter<<<M / 128, 256, FS_TOTAL>>>(X, E, out);
    vq_capture<<<512, 256>>>(X);
    vq_refine<<<256, 256>>>(X, E, out);
    vq_rowscan<<<128, 256>>>(X, E, out);
    vq_finish<<<1, 1>>>(out, out_size - 1);
}